// round 10
// baseline (speedup 1.0000x reference)
#include <cuda_runtime.h>
#include <cuda_bf16.h>

// QuadrupletMarginMiner dense-mask: out[i,j,k,n] = 96^4 booleans as float32.
//   sames[i,j] = share-label & i!=j ; diffs[i,n] = !share-label (diag kept)
//   viol[i,p,n] = (mat[i,n] - mat[i,p]) <= 0.3, mat = -cosine(logits, feat2)
//   out = sames[i,j] & sames[i,k] & (j<k) & diffs[i,n] & (viol[i,j,n]|viol[i,k,n])
//
// SINGLE fused kernel. Each block (i, jg) redundantly computes row i's tiny
// tables (cosine row + label masks + 96-bit violation masks) into shared
// memory (~1-2K cycles), then expands 12 consecutive j-slabs of the 340 MB
// float output with 36 independent streaming STG.128 per thread.

#define NB 96
#define DF 64
#define NC 21
#define MARGIN_F 0.3f
#define JPB 12            // j values per block (NB / gridDim.x = 96/8)

__global__ __launch_bounds__(768) void k_fused(const float* __restrict__ logits,
                                               const float* __restrict__ labels,
                                               const float* __restrict__ feat2,
                                               float4* __restrict__ out) {
    int i   = blockIdx.y;
    int jg  = blockIdx.x;          // 0..7
    int tid = threadIdx.x;

    __shared__ float    sm[NB];            // mat row i
    __shared__ unsigned sh_sames[3];       // 96-bit sames mask for row i
    __shared__ unsigned sh_diff[3];        // 96-bit diffs mask for row i
    __shared__ unsigned sh_viol[NB][3];    // viol[i][p][w]

    // ---- phase 1: row-i tables (threads 0..95 = warps 0..2, full warps) ----
    if (tid < NB) {
        float nx = 0.f, ny = 0.f, dot = 0.f;
#pragma unroll
        for (int d = 0; d < DF; d++) {
            float a = logits[i * DF + d];    // uniform: L1/const-path broadcast
            float b = feat2[tid * DF + d];
            nx += a * a;
            ny += b * b;
            dot += a * b;
        }
        float denom = fmaxf(sqrtf(nx), 1e-12f) * fmaxf(sqrtf(ny), 1e-12f);
        sm[tid] = -(dot / denom);

        float sdot = 0.f;
#pragma unroll
        for (int c = 0; c < NC; c++)
            sdot += labels[i * NC + c] * labels[tid * NC + c];
        bool s = sdot > 0.f;

        unsigned bs = __ballot_sync(0xFFFFFFFFu, s && (tid != i)); // sames
        unsigned bd = __ballot_sync(0xFFFFFFFFu, !s);              // diffs
        if ((tid & 31) == 0) {
            sh_sames[tid >> 5] = bs;
            sh_diff[tid >> 5]  = bd;
        }
    }
    __syncthreads();

    if (tid < NB) {
        float mp = sm[tid];
        unsigned w0 = 0, w1 = 0, w2 = 0;
#pragma unroll
        for (int neg = 0; neg < 32; neg++)
            if ((sm[neg] - mp) <= MARGIN_F) w0 |= 1u << neg;
#pragma unroll
        for (int neg = 0; neg < 32; neg++)
            if ((sm[32 + neg] - mp) <= MARGIN_F) w1 |= 1u << neg;
#pragma unroll
        for (int neg = 0; neg < 32; neg++)
            if ((sm[64 + neg] - mp) <= MARGIN_F) w2 |= 1u << neg;
        sh_viol[tid][0] = w0;
        sh_viol[tid][1] = w1;
        sh_viol[tid][2] = w2;
    }
    __syncthreads();

    // ---- phase 2: expand 12 j-slabs (36 KB each, contiguous 432 KB) ----
    // thread: k = tid>>3 (fixed), sub = tid&7 -> nibble [4*sub..+3] of each
    // 96-bit row mask. 8-thread groups store full aligned 128B segments.
    int k     = tid >> 3;
    int sub   = tid & 7;
    int shift = sub * 4;

    unsigned sik = (sh_sames[k >> 5] >> (k & 31)) & 1u;
    unsigned d0 = sh_diff[0], d1 = sh_diff[1], d2 = sh_diff[2];
    unsigned dvk0 = d0 & sh_viol[k][0];   // d_w & vk_w (per-thread invariant)
    unsigned dvk1 = d1 & sh_viol[k][1];
    unsigned dvk2 = d2 & sh_viol[k][2];

    int j0 = jg * JPB;
    float4* base = out + (size_t)(i * NB + j0) * (NB * NB / 4) + k * 24 + sub;

#pragma unroll
    for (int jj = 0; jj < JPB; jj++) {
        int j = j0 + jj;
        unsigned sij = (sh_sames[j >> 5] >> (j & 31)) & 1u;  // uniform

        unsigned m0 = 0u, m1 = 0u, m2 = 0u;
        if (sij & sik & (unsigned)(j < k)) {
            // row_w = d_w & (vj_w | vk_w) = (d_w & vj_w) | dvk_w
            m0 = (((d0 & sh_viol[j][0]) | dvk0) >> shift) & 0xFu;
            m1 = (((d1 & sh_viol[j][1]) | dvk1) >> shift) & 0xFu;
            m2 = (((d2 & sh_viol[j][2]) | dvk2) >> shift) & 0xFu;
        }

        float4 q0, q1, q2;
        q0.x = (m0 & 1u) ? 1.0f : 0.0f;  q0.y = (m0 & 2u) ? 1.0f : 0.0f;
        q0.z = (m0 & 4u) ? 1.0f : 0.0f;  q0.w = (m0 & 8u) ? 1.0f : 0.0f;
        q1.x = (m1 & 1u) ? 1.0f : 0.0f;  q1.y = (m1 & 2u) ? 1.0f : 0.0f;
        q1.z = (m1 & 4u) ? 1.0f : 0.0f;  q1.w = (m1 & 8u) ? 1.0f : 0.0f;
        q2.x = (m2 & 1u) ? 1.0f : 0.0f;  q2.y = (m2 & 2u) ? 1.0f : 0.0f;
        q2.z = (m2 & 4u) ? 1.0f : 0.0f;  q2.w = (m2 & 8u) ? 1.0f : 0.0f;

        __stcs(base,      q0);   // n bits [ 0..31]
        __stcs(base + 8,  q1);   // n bits [32..63]
        __stcs(base + 16, q2);   // n bits [64..95]
        base += NB * NB / 4;     // next j slab
    }
}

extern "C" void kernel_launch(void* const* d_in, const int* in_sizes, int n_in,
                              void* d_out, int out_size) {
    const float* logits = (const float*)d_in[0];  // [96, 64]
    const float* labels = (const float*)d_in[1];  // [96, 21]
    const float* feat2  = (const float*)d_in[2];  // [96, 64]

    k_fused<<<dim3(NB / JPB, NB), 768>>>(logits, labels, feat2,
                                         (float4*)d_out);
}

// round 11
// speedup vs baseline: 1.9098x; 1.9098x over previous
#include <cuda_runtime.h>
#include <cuda_bf16.h>

// QuadrupletMarginMiner dense-mask: out[i,j,k,n] = 96^4 booleans as float32.
//   sames[i,j] = share-label & i!=j ; diffs[i,n] = !share-label (diag kept)
//   viol[i,p,n] = (mat[i,n] - mat[i,p]) <= 0.3, mat = -cosine(logits, feat2)
//   out = sames[i,j] & sames[i,k] & (j<k) & diffs[i,n] & (viol[i,j,n]|viol[i,k,n])
// Two kernels: tiny bitmask precompute, then a store-bandwidth-bound expansion
// (340 MB float output). R11: 256-thread blocks (8 blocks/SM -> 100%
// theoretical occupancy), 9 independent coalesced STG.128 per thread.

#define NB 96
#define DF 64
#define NC 21
#define MARGIN_F 0.3f

__device__ unsigned g_viol[NB][NB][3];    // 96-bit viol mask per (i,p)
__device__ unsigned g_sames[NB][3];       // 96-bit sames mask per i
__device__ unsigned g_diff[NB][3];        // 96-bit diffs mask per i

// ---- fused precompute: cosine row -> shared -> viol masks + label masks ----
__global__ __launch_bounds__(NB) void k_pre(const float* __restrict__ logits,
                                            const float* __restrict__ labels,
                                            const float* __restrict__ feat2) {
    int i = blockIdx.x;
    int j = threadIdx.x;
    __shared__ float sm[NB];

    float nx = 0.f, ny = 0.f, dot = 0.f;
#pragma unroll
    for (int d = 0; d < DF; d++) {
        float a = logits[i * DF + d];   // broadcast across block (L1 hit)
        float b = feat2[j * DF + d];
        nx += a * a;
        ny += b * b;
        dot += a * b;
    }
    float denom = fmaxf(sqrtf(nx), 1e-12f) * fmaxf(sqrtf(ny), 1e-12f);
    sm[j] = -(dot / denom);

    float sdot = 0.f;
#pragma unroll
    for (int c = 0; c < NC; c++)
        sdot += labels[i * NC + c] * labels[j * NC + c];
    bool s = sdot > 0.f;

    unsigned bs = __ballot_sync(0xFFFFFFFFu, s && (j != i));  // sames: no diag
    unsigned bd = __ballot_sync(0xFFFFFFFFu, !s);             // diffs: diag kept
    if ((j & 31) == 0) {
        g_sames[i][j >> 5] = bs;
        g_diff[i][j >> 5]  = bd;
    }

    __syncthreads();

    float mp = sm[j];
    unsigned w0 = 0, w1 = 0, w2 = 0;
#pragma unroll
    for (int neg = 0; neg < 32; neg++)
        if ((sm[neg] - mp) <= MARGIN_F) w0 |= 1u << neg;
#pragma unroll
    for (int neg = 0; neg < 32; neg++)
        if ((sm[32 + neg] - mp) <= MARGIN_F) w1 |= 1u << neg;
#pragma unroll
    for (int neg = 0; neg < 32; neg++)
        if ((sm[64 + neg] - mp) <= MARGIN_F) w2 |= 1u << neg;

    g_viol[i][j][0] = w0;
    g_viol[i][j][1] = w1;
    g_viol[i][j][2] = w2;
}

// ---- expand masks -> 340 MB float output ----
// grid (j, i); block = one (i,j) pair = 9216 floats = 2304 float4.
// 256 threads: k0 = tid>>3 (0..31), sub = tid&7 -> nibble [4*sub..+3].
// Thread covers k = k0 + 32*s for s=0..2; per (k) the 3 n-words -> 9
// independent STG.128. Since k0 < 32, sames word index == s (no division
// anywhere). 8-thread groups store full aligned 128B segments, streaming.
__global__ __launch_bounds__(256, 8) void k_out(float4* __restrict__ out) {
    int j   = blockIdx.x;
    int i   = blockIdx.y;
    int tid = threadIdx.x;
    int k0  = tid >> 3;       // 0..31
    int sub = tid & 7;
    int shift = sub * 4;

    unsigned sij = (g_sames[i][j >> 5] >> (j & 31)) & 1u;
    unsigned sw0 = g_sames[i][0], sw1 = g_sames[i][1], sw2 = g_sames[i][2];
    unsigned d0 = g_diff[i][0], d1 = g_diff[i][1], d2 = g_diff[i][2];
    // j-invariant halves of row_w = (d_w & vj_w) | (d_w & vk_w)
    unsigned dvj0 = d0 & g_viol[i][j][0];
    unsigned dvj1 = d1 & g_viol[i][j][1];
    unsigned dvj2 = d2 & g_viol[i][j][2];

    float4* base = out + (size_t)(i * NB + j) * (NB * NB / 4) + k0 * 24 + sub;

#pragma unroll
    for (int s = 0; s < 3; s++) {
        int k = k0 + 32 * s;
        unsigned sw = (s == 0) ? sw0 : ((s == 1) ? sw1 : sw2);
        unsigned sik = (sw >> k0) & 1u;

        unsigned m0 = 0u, m1 = 0u, m2 = 0u;
        if (sij & sik & (unsigned)(j < k)) {
            m0 = ((dvj0 | (d0 & g_viol[i][k][0])) >> shift) & 0xFu;
            m1 = ((dvj1 | (d1 & g_viol[i][k][1])) >> shift) & 0xFu;
            m2 = ((dvj2 | (d2 & g_viol[i][k][2])) >> shift) & 0xFu;
        }

        float4 q0, q1, q2;
        q0.x = (m0 & 1u) ? 1.0f : 0.0f;  q0.y = (m0 & 2u) ? 1.0f : 0.0f;
        q0.z = (m0 & 4u) ? 1.0f : 0.0f;  q0.w = (m0 & 8u) ? 1.0f : 0.0f;
        q1.x = (m1 & 1u) ? 1.0f : 0.0f;  q1.y = (m1 & 2u) ? 1.0f : 0.0f;
        q1.z = (m1 & 4u) ? 1.0f : 0.0f;  q1.w = (m1 & 8u) ? 1.0f : 0.0f;
        q2.x = (m2 & 1u) ? 1.0f : 0.0f;  q2.y = (m2 & 2u) ? 1.0f : 0.0f;
        q2.z = (m2 & 4u) ? 1.0f : 0.0f;  q2.w = (m2 & 8u) ? 1.0f : 0.0f;

        float4* p = base + s * (32 * 24);   // k advances by 32 -> +768 quads
        __stcs(p,      q0);   // n bits [ 0..31]
        __stcs(p + 8,  q1);   // n bits [32..63]
        __stcs(p + 16, q2);   // n bits [64..95]
    }
}

extern "C" void kernel_launch(void* const* d_in, const int* in_sizes, int n_in,
                              void* d_out, int out_size) {
    const float* logits = (const float*)d_in[0];  // [96, 64]
    const float* labels = (const float*)d_in[1];  // [96, 21]
    const float* feat2  = (const float*)d_in[2];  // [96, 64]

    k_pre<<<NB, NB>>>(logits, labels, feat2);
    k_out<<<dim3(NB, NB), 256>>>((float4*)d_out);
}